// round 14
// baseline (speedup 1.0000x reference)
#include <cuda_runtime.h>
#include <cuda_bf16.h>
#include <math.h>

#define NTOK 4096
#define BD 16      // q/k projection dim
#define CC 128     // value channels
#define BM 64      // query tile
#define BN 64      // key tile
#define NB 4       // batch
#define NT (NTOK / BN)   // 64 key tiles

typedef unsigned long long u64;
typedef unsigned int u32;

// ---------------- packed f32x2 helpers ----------------
__device__ __forceinline__ u64 pk2(float lo, float hi) {
    u64 r;
    asm("mov.b64 %0, {%1, %2};" : "=l"(r) : "r"(__float_as_uint(lo)), "r"(__float_as_uint(hi)));
    return r;
}
__device__ __forceinline__ void upk2(float& lo, float& hi, u64 v) {
    u32 a, b;
    asm("mov.b64 {%0, %1}, %2;" : "=r"(a), "=r"(b) : "l"(v));
    lo = __uint_as_float(a); hi = __uint_as_float(b);
}
__device__ __forceinline__ void fma2(u64& d, u64 a, u64 b) {
    asm("fma.rn.f32x2 %0, %1, %2, %3;" : "=l"(d) : "l"(a), "l"(b), "l"(d));
}
__device__ __forceinline__ u64 d2u(double d) { return (u64)__double_as_longlong(d); }

// pack two f32 -> bf16x2 (lo at low half)
__device__ __forceinline__ u32 cvt2bf(float lo, float hi) {
    u32 r;
    asm("cvt.rn.bf16x2.f32 %0, %1, %2;" : "=r"(r) : "f"(hi), "f"(lo));
    return r;
}

// ---------------- cp.async ----------------
__device__ __forceinline__ void cp16s(u32 ds, const void* src) {
    asm volatile("cp.async.cg.shared.global [%0], [%1], 16;" :: "r"(ds), "l"(src));
}
__device__ __forceinline__ void cp4s(u32 ds, const void* src) {
    asm volatile("cp.async.ca.shared.global [%0], [%1], 4;" :: "r"(ds), "l"(src));
}
#define CP_COMMIT() asm volatile("cp.async.commit_group;" ::: "memory")
#define CP_WAIT1()  asm volatile("cp.async.wait_group 1;" ::: "memory")

// ---------------- ldmatrix / mma.sync ----------------
#define LDSM_X4(r0, r1, r2, r3, addr) \
    asm volatile("ldmatrix.sync.aligned.m8n8.x4.shared.b16 {%0,%1,%2,%3}, [%4];" \
                 : "=r"(r0), "=r"(r1), "=r"(r2), "=r"(r3) : "r"(addr))
#define LDSM_X4T(r0, r1, r2, r3, addr) \
    asm volatile("ldmatrix.sync.aligned.m8n8.x4.trans.shared.b16 {%0,%1,%2,%3}, [%4];" \
                 : "=r"(r0), "=r"(r1), "=r"(r2), "=r"(r3) : "r"(addr))
#define MMA_BF16(c0, c1, c2, c3, a0, a1, a2, a3, b0, b1) \
    asm volatile("mma.sync.aligned.m16n8k16.row.col.f32.bf16.bf16.f32 " \
                 "{%0,%1,%2,%3}, {%4,%5,%6,%7}, {%8,%9}, {%0,%1,%2,%3};" \
                 : "+f"(c0), "+f"(c1), "+f"(c2), "+f"(c3) \
                 : "r"(a0), "r"(a1), "r"(a2), "r"(a3), "r"(b0), "r"(b1))

// scratch (allocation-free rule: __device__ globals)
__device__ __align__(16) float g_q[NB * NTOK * BD];
__device__ __align__(16) float g_k[NB * NTOK * BD];
__device__ __align__(16) __nv_bfloat16 g_vb[NB * NTOK * CC];   // token-major bf16 V

// ---------------------------------------------------------------------------
// fused projections. blockIdx.x < 16  -> q/k projection (one token per thread)
//                    blockIdx.x >= 16 -> v projection -> token-major bf16
// ---------------------------------------------------------------------------
__global__ void __launch_bounds__(256)
proj_kernel(const float* __restrict__ x,
            const float* __restrict__ Wq, const float* __restrict__ bq,
            const float* __restrict__ Wk, const float* __restrict__ bk,
            const float* __restrict__ xh,
            const float* __restrict__ Wv, const float* __restrict__ bv)
{
    __shared__ float sbuf[128 * 64 + 16 * 128];
    int tid = threadIdx.x;
    int b = blockIdx.y;

    if (blockIdx.x < 16) {
        float* sWq = sbuf;
        float* sWk = sbuf + 1024;
        float* sb  = sbuf + 2048;
        for (int e = tid; e < 1024; e += 256) { sWq[e] = Wq[e]; sWk[e] = Wk[e]; }
        if (tid < 16) { sb[tid] = bq[tid]; sb[16 + tid] = bk[tid]; }
        __syncthreads();

        int n = blockIdx.x * 256 + tid;
        float xc[64];
#pragma unroll
        for (int c = 0; c < 64; ++c) xc[c] = x[((size_t)b * 64 + c) * NTOK + n];

        float* qo = g_q + ((size_t)b * NTOK + n) * BD;
        float* ko = g_k + ((size_t)b * NTOK + n) * BD;
#pragma unroll
        for (int d4 = 0; d4 < 4; ++d4) {
            float q[4], k[4];
#pragma unroll
            for (int r = 0; r < 4; ++r) { q[r] = sb[d4 * 4 + r]; k[r] = sb[16 + d4 * 4 + r]; }
#pragma unroll
            for (int c = 0; c < 64; ++c) {
#pragma unroll
                for (int r = 0; r < 4; ++r) {
                    q[r] += sWq[(d4 * 4 + r) * 64 + c] * xc[c];
                    k[r] += sWk[(d4 * 4 + r) * 64 + c] * xc[c];
                }
            }
            ((float4*)qo)[d4] = make_float4(q[0], q[1], q[2], q[3]);
            ((float4*)ko)[d4] = make_float4(k[0], k[1], k[2], k[3]);
        }
    } else {
        float (*Xs)[64]  = (float (*)[64])sbuf;
        float (*Wt)[128] = (float (*)[128])(sbuf + 8192);
        int n0 = (blockIdx.x - 16) * 64;
        int nl = tid & 63;
        int g  = tid >> 6;

        for (int e = tid; e < 128 * 64; e += 256) {
            int c = e >> 6, nn = e & 63;
            Xs[c][nn] = xh[((size_t)b * 128 + c) * NTOK + n0 + nn];
        }

        float acc[32];
#pragma unroll
        for (int i = 0; i < 32; ++i) acc[i] = 0.f;

        for (int cc0 = 0; cc0 < 128; cc0 += 16) {
            __syncthreads();
            for (int e = tid; e < 16 * 128; e += 256) {
                int c = e >> 4, cp = e & 15;
                Wt[cp][c] = Wv[c * 128 + cc0 + cp];
            }
            __syncthreads();
#pragma unroll
            for (int cp = 0; cp < 16; ++cp) {
                float xv = Xs[cc0 + cp][nl];
                const float4* w4 = (const float4*)&Wt[cp][g * 32];
#pragma unroll
                for (int q = 0; q < 8; ++q) {
                    float4 w = w4[q];
                    acc[q * 4 + 0] += xv * w.x;
                    acc[q * 4 + 1] += xv * w.y;
                    acc[q * 4 + 2] += xv * w.z;
                    acc[q * 4 + 3] += xv * w.w;
                }
            }
        }

        __nv_bfloat16* vo = g_vb + ((size_t)b * NTOK + n0 + nl) * CC + g * 32;
#pragma unroll
        for (int q = 0; q < 8; ++q) {
            int c0 = g * 32 + q * 4;
            __nv_bfloat162 h0 = __floats2bfloat162_rn(acc[q * 4 + 0] + bv[c0 + 0],
                                                      acc[q * 4 + 1] + bv[c0 + 1]);
            __nv_bfloat162 h1 = __floats2bfloat162_rn(acc[q * 4 + 2] + bv[c0 + 2],
                                                      acc[q * 4 + 3] + bv[c0 + 3]);
            *(__nv_bfloat162*)(vo + q * 4)     = h0;
            *(__nv_bfloat162*)(vo + q * 4 + 2) = h1;
        }
    }
}

// ---------------------------------------------------------------------------
// flash attention, BM=64, 128 threads (4 warps), 2 CTAs/SM for phase overlap.
// QK+exp fp32 FFMA2; PV bf16 mma.sync with fp32 accumulators across tiles.
// ---------------------------------------------------------------------------
#define QS_OFF   0
#define QS_STR   136                        // floats per Qs row (64 dup q + pad)
#define KS_OFF   (16 * QS_STR * 4)          // 8704
#define KS_STRF  68                         // floats per K row
#define KS_BUFB  (16 * KS_STRF * 4)         // 4352
#define P_OFF    (KS_OFF + 2 * KS_BUFB)     // 17408
#define P_STRB   144                        // bytes per P row (64 bf16 + pad)
#define V_OFF    (P_OFF + BM * P_STRB)      // 26624
#define V_STRB   272                        // bytes per V row (128 bf16 + pad)
#define V_BUFB   (BN * V_STRB)              // 17408
#define L_OFF    (V_OFF + 2 * V_BUFB)       // 61440
#define SMEM_BYTES (L_OFF + 256)            // 61696  (x2 CTA = 123392 <= 228KB)

__global__ void __launch_bounds__(128, 2)
flash_kernel(const float* __restrict__ xh,
             const float* __restrict__ gamma,
             float* __restrict__ out)
{
    extern __shared__ __align__(16) char smb[];
    u32 sb = (u32)__cvta_generic_to_shared(smb);

    int tid  = threadIdx.x;
    int warp = tid >> 5, lane = tid & 31;
    int tx = tid & 15, ty = tid >> 4;        // ty 0..7: 8 queries each; tx: keys 4tx..4tx+3
    int b  = blockIdx.y;
    int i0 = blockIdx.x * BM;

    const float* qb = g_q + (size_t)b * NTOK * BD;
    const float* kb = g_k + (size_t)b * NTOK * BD;
    const __nv_bfloat16* vb = g_vb + (size_t)b * NTOK * CC;

    // ---- prologue: stage tile 0 K (fp32 transposed) + V (bf16 token rows)
#pragma unroll
    for (int it = 0; it < 8; ++it) {
        int e = tid + it * 128;
        int tok = e >> 4, d = e & 15;
        cp4s(sb + KS_OFF + (u32)(d * KS_STRF + tok) * 4, kb + (size_t)tok * BD + d);
    }
#pragma unroll
    for (int it = 0; it < 8; ++it) {
        int e = tid + it * 128;
        int k = e >> 4, c16 = e & 15;
        cp16s(sb + V_OFF + (u32)(k * V_STRB + c16 * 16), vb + (size_t)k * CC + c16 * 8);
    }
    CP_COMMIT();

    // ---- Q: load, transpose to [d][q], duplicate pairs for f32x2
    {
        const float4* qb4 = (const float4*)qb;
#pragma unroll
        for (int it = 0; it < 2; ++it) {
            int e = tid + it * 128;
            int tok = e >> 2, dq = e & 3;
            float4 v = qb4[(size_t)(i0 + tok) * 4 + dq];
            float vr[4] = {v.x, v.y, v.z, v.w};
#pragma unroll
            for (int r = 0; r < 4; ++r) {
                float* row = (float*)(smb + QS_OFF + (size_t)(dq * 4 + r) * QS_STR * 4);
                row[2 * tok]     = vr[r];
                row[2 * tok + 1] = vr[r];
            }
        }
    }

    float acc[16][4];                        // 16 n-blocks x m16n8 fragment
#pragma unroll
    for (int nb = 0; nb < 16; ++nb)
#pragma unroll
        for (int r = 0; r < 4; ++r) acc[nb][r] = 0.f;

    float l[8];
#pragma unroll
    for (int ii = 0; ii < 8; ++ii) l[ii] = 0.f;

    // ldmatrix lane addressing (constant per thread)
    int a_row  = (lane & 7) + ((lane >> 3) & 1) * 8;
    int a_csel = ((lane >> 4) & 1) * 16;
    u32 a_base = sb + P_OFF + (u32)((warp * 16 + a_row) * P_STRB + a_csel);
    int b_krow = (lane & 7) + ((lane >> 3) & 1) * 8;
    int b_csel = ((lane >> 4) & 1) * 16;

    for (int t = 0; t < NT; ++t) {
        __syncthreads();   // prior tile's P/V reads done before overwrite

        if (t + 1 < NT) {
            int j1 = (t + 1) * BN;
            u32 kd = sb + KS_OFF + (u32)(((t + 1) & 1) * KS_BUFB);
            u32 vd = sb + V_OFF + (u32)(((t + 1) & 1) * V_BUFB);
#pragma unroll
            for (int it = 0; it < 8; ++it) {
                int e = tid + it * 128;
                int tok = e >> 4, d = e & 15;
                cp4s(kd + (u32)(d * KS_STRF + tok) * 4, kb + (size_t)(j1 + tok) * BD + d);
            }
#pragma unroll
            for (int it = 0; it < 8; ++it) {
                int e = tid + it * 128;
                int k = e >> 4, c16 = e & 15;
                cp16s(vd + (u32)(k * V_STRB + c16 * 16), vb + (size_t)(j1 + k) * CC + c16 * 8);
            }
        }
        CP_COMMIT();
        CP_WAIT1();        // tile t's K/V resident
        __syncthreads();

        // ---- QK scores (fp32 FFMA2): 8 queries x 4 consecutive keys
        const float* Ksb = (const float*)(smb + KS_OFF + (t & 1) * KS_BUFB);
        u64 s2[8][2];
#pragma unroll
        for (int ii = 0; ii < 8; ++ii) { s2[ii][0] = 0ull; s2[ii][1] = 0ull; }
#pragma unroll
        for (int d = 0; d < 16; ++d) {
            const double2* q2 = (const double2*)(smb + QS_OFF + (size_t)d * QS_STR * 4);
            double2 qa = q2[ty * 4 + 0];
            double2 qc = q2[ty * 4 + 1];
            double2 qe = q2[ty * 4 + 2];
            double2 qg = q2[ty * 4 + 3];
            u64 qv[8] = { d2u(qa.x), d2u(qa.y), d2u(qc.x), d2u(qc.y),
                          d2u(qe.x), d2u(qe.y), d2u(qg.x), d2u(qg.y) };
            float4 k4 = *(const float4*)(Ksb + d * KS_STRF + tx * 4);
            u64 kv0 = pk2(k4.x, k4.y), kv1 = pk2(k4.z, k4.w);
#pragma unroll
            for (int ii = 0; ii < 8; ++ii) {
                fma2(s2[ii][0], qv[ii], kv0);
                fma2(s2[ii][1], qv[ii], kv1);
            }
        }

        // ---- exp (fp32), pack bf16 into P[64 q][64 k], accumulate l
#pragma unroll
        for (int ii = 0; ii < 8; ++ii) {
            float s0, s1, sA, sB;
            upk2(s0, s1, s2[ii][0]);
            upk2(sA, sB, s2[ii][1]);
            float p0 = __expf(s0), p1 = __expf(s1);
            float p2 = __expf(sA), p3 = __expf(sB);
            l[ii] += (p0 + p1) + (p2 + p3);
            u32 lo = cvt2bf(p0, p1);
            u32 hi = cvt2bf(p2, p3);
            u64 w = (u64)lo | ((u64)hi << 32);
            *(u64*)(smb + P_OFF + (size_t)(ty * 8 + ii) * P_STRB + tx * 8) = w;
        }
        __syncthreads();   // P complete, V[t&1] resident

        // ---- PV via mma.sync: warp w rows 16w..16w+15, all 128 channels
        {
            u32 vbase = sb + V_OFF + (u32)((t & 1) * V_BUFB);
            u32 A[4][4];
#pragma unroll
            for (int ks = 0; ks < 4; ++ks)
                LDSM_X4(A[ks][0], A[ks][1], A[ks][2], A[ks][3], a_base + ks * 32);
#pragma unroll
            for (int nbp = 0; nbp < 8; ++nbp) {
#pragma unroll
                for (int ks = 0; ks < 4; ++ks) {
                    u32 b0, b1, b2, b3;
                    u32 baddr = vbase + (u32)((ks * 16 + b_krow) * V_STRB + nbp * 32 + b_csel);
                    LDSM_X4T(b0, b1, b2, b3, baddr);
                    MMA_BF16(acc[nbp * 2][0], acc[nbp * 2][1], acc[nbp * 2][2], acc[nbp * 2][3],
                             A[ks][0], A[ks][1], A[ks][2], A[ks][3], b0, b1);
                    MMA_BF16(acc[nbp * 2 + 1][0], acc[nbp * 2 + 1][1],
                             acc[nbp * 2 + 1][2], acc[nbp * 2 + 1][3],
                             A[ks][0], A[ks][1], A[ks][2], A[ks][3], b2, b3);
                }
            }
        }
    }

    // ---- l: reduce across the 16 tx lanes, publish per query row
#pragma unroll
    for (int ii = 0; ii < 8; ++ii) {
#pragma unroll
        for (int off = 8; off >= 1; off >>= 1)
            l[ii] += __shfl_xor_sync(0xffffffffu, l[ii], off, 16);
    }
    if (tx == 0) {
        float* Ls = (float*)(smb + L_OFF);
#pragma unroll
        for (int ii = 0; ii < 8; ++ii) Ls[ty * 8 + ii] = l[ii];
    }
    __syncthreads();

    // ---- epilogue: out = gamma * acc / l + xh
    {
        const float* Ls = (const float*)(smb + L_OFF);
        float g = gamma[0];
        int r0 = warp * 16 + (lane >> 2);
        int r1 = r0 + 8;
        float inv0 = g / Ls[r0];
        float inv1 = g / Ls[r1];
#pragma unroll
        for (int nb = 0; nb < 16; ++nb) {
            int ch = nb * 8 + (lane & 3) * 2;
            size_t g00 = ((size_t)(b * CC + ch)) * NTOK + i0 + r0;
            size_t g01 = g00 + NTOK;
            out[g00]     = acc[nb][0] * inv0 + xh[g00];
            out[g01]     = acc[nb][1] * inv0 + xh[g01];
            out[g00 + 8] = acc[nb][2] * inv1 + xh[g00 + 8];
            out[g01 + 8] = acc[nb][3] * inv1 + xh[g01 + 8];
        }
    }
}

// ---------------------------------------------------------------------------
extern "C" void kernel_launch(void* const* d_in, const int* in_sizes, int n_in,
                              void* d_out, int out_size)
{
    const float* x     = (const float*)d_in[0];
    const float* xh    = (const float*)d_in[1];
    const float* Wq    = (const float*)d_in[2];
    const float* bq    = (const float*)d_in[3];
    const float* Wk    = (const float*)d_in[4];
    const float* bk    = (const float*)d_in[5];
    const float* Wv    = (const float*)d_in[6];
    const float* bv    = (const float*)d_in[7];
    const float* gamma = (const float*)d_in[8];
    float* out = (float*)d_out;

    (void)in_sizes; (void)n_in; (void)out_size;

    cudaFuncSetAttribute(flash_kernel, cudaFuncAttributeMaxDynamicSharedMemorySize, SMEM_BYTES);

    proj_kernel<<<dim3(16 + NTOK / 64, NB), 256>>>(x, Wq, bq, Wk, bk, xh, Wv, bv);
    flash_kernel<<<dim3(NTOK / BM, NB), 128, SMEM_BYTES>>>(xh, gamma, out);
}

// round 15
// speedup vs baseline: 1.5697x; 1.5697x over previous
#include <cuda_runtime.h>
#include <cuda_bf16.h>
#include <math.h>

#define NTOK 4096
#define BD 16      // q/k projection dim
#define CC 128     // value channels
#define BM 64      // query tile
#define BN 64      // key tile
#define NB 4       // batch
#define NT (NTOK / BN)   // 64 key tiles

typedef unsigned long long u64;
typedef unsigned int u32;

// pack two f32 -> bf16x2 (lo at low half)
__device__ __forceinline__ u32 cvt2bf(float lo, float hi) {
    u32 r;
    asm("cvt.rn.bf16x2.f32 %0, %1, %2;" : "=r"(r) : "f"(hi), "f"(lo));
    return r;
}

// ---------------- cp.async ----------------
__device__ __forceinline__ void cp16s(u32 ds, const void* src) {
    asm volatile("cp.async.cg.shared.global [%0], [%1], 16;" :: "r"(ds), "l"(src));
}
#define CP_COMMIT() asm volatile("cp.async.commit_group;" ::: "memory")
#define CP_WAIT1()  asm volatile("cp.async.wait_group 1;" ::: "memory")

// ---------------- ldmatrix / mma.sync ----------------
#define LDSM_X4(r0, r1, r2, r3, addr) \
    asm volatile("ldmatrix.sync.aligned.m8n8.x4.shared.b16 {%0,%1,%2,%3}, [%4];" \
                 : "=r"(r0), "=r"(r1), "=r"(r2), "=r"(r3) : "r"(addr))
#define LDSM_X4T(r0, r1, r2, r3, addr) \
    asm volatile("ldmatrix.sync.aligned.m8n8.x4.trans.shared.b16 {%0,%1,%2,%3}, [%4];" \
                 : "=r"(r0), "=r"(r1), "=r"(r2), "=r"(r3) : "r"(addr))
#define MMA_BF16(c0, c1, c2, c3, a0, a1, a2, a3, b0, b1) \
    asm volatile("mma.sync.aligned.m16n8k16.row.col.f32.bf16.bf16.f32 " \
                 "{%0,%1,%2,%3}, {%4,%5,%6,%7}, {%8,%9}, {%0,%1,%2,%3};" \
                 : "+f"(c0), "+f"(c1), "+f"(c2), "+f"(c3) \
                 : "r"(a0), "r"(a1), "r"(a2), "r"(a3), "r"(b0), "r"(b1))

// scratch (allocation-free rule: __device__ globals)
__device__ __align__(16) float g_q[NB * NTOK * BD];
__device__ __align__(16) __nv_bfloat16 g_khi[NB * BD * NTOK];  // [b][d][tok]
__device__ __align__(16) __nv_bfloat16 g_klo[NB * BD * NTOK];  // [b][d][tok]
__device__ __align__(16) __nv_bfloat16 g_vb[NB * NTOK * CC];   // token-major bf16 V

// ---------------------------------------------------------------------------
// fused projections. blockIdx.x < 16  -> q/k projection (one token per thread);
//   k written as bf16 hi/lo in [b][d][tok] layout for flash cp.async rows.
// blockIdx.x >= 16 -> v projection -> token-major bf16
// ---------------------------------------------------------------------------
__global__ void __launch_bounds__(256)
proj_kernel(const float* __restrict__ x,
            const float* __restrict__ Wq, const float* __restrict__ bq,
            const float* __restrict__ Wk, const float* __restrict__ bk,
            const float* __restrict__ xh,
            const float* __restrict__ Wv, const float* __restrict__ bv)
{
    __shared__ float sbuf[128 * 64 + 16 * 128];
    int tid = threadIdx.x;
    int b = blockIdx.y;

    if (blockIdx.x < 16) {
        float* sWq = sbuf;
        float* sWk = sbuf + 1024;
        float* sb  = sbuf + 2048;
        for (int e = tid; e < 1024; e += 256) { sWq[e] = Wq[e]; sWk[e] = Wk[e]; }
        if (tid < 16) { sb[tid] = bq[tid]; sb[16 + tid] = bk[tid]; }
        __syncthreads();

        int n = blockIdx.x * 256 + tid;
        float xc[64];
#pragma unroll
        for (int c = 0; c < 64; ++c) xc[c] = x[((size_t)b * 64 + c) * NTOK + n];

        float* qo = g_q + ((size_t)b * NTOK + n) * BD;
#pragma unroll
        for (int d4 = 0; d4 < 4; ++d4) {
            float q[4], k[4];
#pragma unroll
            for (int r = 0; r < 4; ++r) { q[r] = sb[d4 * 4 + r]; k[r] = sb[16 + d4 * 4 + r]; }
#pragma unroll
            for (int c = 0; c < 64; ++c) {
#pragma unroll
                for (int r = 0; r < 4; ++r) {
                    q[r] += sWq[(d4 * 4 + r) * 64 + c] * xc[c];
                    k[r] += sWk[(d4 * 4 + r) * 64 + c] * xc[c];
                }
            }
            ((float4*)qo)[d4] = make_float4(q[0], q[1], q[2], q[3]);
#pragma unroll
            for (int r = 0; r < 4; ++r) {
                int d = d4 * 4 + r;
                __nv_bfloat16 kh = __float2bfloat16(k[r]);
                float krem = k[r] - __bfloat162float(kh);
                g_khi[((size_t)b * BD + d) * NTOK + n] = kh;
                g_klo[((size_t)b * BD + d) * NTOK + n] = __float2bfloat16(krem);
            }
        }
    } else {
        float (*Xs)[64]  = (float (*)[64])sbuf;
        float (*Wt)[128] = (float (*)[128])(sbuf + 8192);
        int n0 = (blockIdx.x - 16) * 64;
        int nl = tid & 63;
        int g  = tid >> 6;

        for (int e = tid; e < 128 * 64; e += 256) {
            int c = e >> 6, nn = e & 63;
            Xs[c][nn] = xh[((size_t)b * 128 + c) * NTOK + n0 + nn];
        }

        float acc[32];
#pragma unroll
        for (int i = 0; i < 32; ++i) acc[i] = 0.f;

        for (int cc0 = 0; cc0 < 128; cc0 += 16) {
            __syncthreads();
            for (int e = tid; e < 16 * 128; e += 256) {
                int c = e >> 4, cp = e & 15;
                Wt[cp][c] = Wv[c * 128 + cc0 + cp];
            }
            __syncthreads();
#pragma unroll
            for (int cp = 0; cp < 16; ++cp) {
                float xv = Xs[cc0 + cp][nl];
                const float4* w4 = (const float4*)&Wt[cp][g * 32];
#pragma unroll
                for (int q = 0; q < 8; ++q) {
                    float4 w = w4[q];
                    acc[q * 4 + 0] += xv * w.x;
                    acc[q * 4 + 1] += xv * w.y;
                    acc[q * 4 + 2] += xv * w.z;
                    acc[q * 4 + 3] += xv * w.w;
                }
            }
        }

        __nv_bfloat16* vo = g_vb + ((size_t)b * NTOK + n0 + nl) * CC + g * 32;
#pragma unroll
        for (int q = 0; q < 8; ++q) {
            int c0 = g * 32 + q * 4;
            __nv_bfloat162 h0 = __floats2bfloat162_rn(acc[q * 4 + 0] + bv[c0 + 0],
                                                      acc[q * 4 + 1] + bv[c0 + 1]);
            __nv_bfloat162 h1 = __floats2bfloat162_rn(acc[q * 4 + 2] + bv[c0 + 2],
                                                      acc[q * 4 + 3] + bv[c0 + 3]);
            *(__nv_bfloat162*)(vo + q * 4)     = h0;
            *(__nv_bfloat162*)(vo + q * 4 + 2) = h1;
        }
    }
}

// ---------------------------------------------------------------------------
// flash attention: QK via bf16x3 mma (fp32-equivalent scores), P kept in
// registers (C-fragment == A-fragment reuse), PV bf16 mma, fp32 accumulators
// across all 64 key tiles. 128 threads (4 warps), 2 CTAs/SM.
// smem: Qhi[64][24b], Qlo, Khi[2][16][72b], Klo, V[2][64][136b]  (bf16 elems)
// ---------------------------------------------------------------------------
#define QH_OFF   0
#define Q_STRB   48                         // bytes per Q row (16 bf16 + pad)
#define QL_OFF   (BM * Q_STRB)              // 3072
#define KH_OFF   (2 * BM * Q_STRB)          // 6144
#define K_STRB   144                        // bytes per K row (64 bf16 + pad)
#define K_BUFB   (16 * K_STRB)              // 2304
#define KL_OFF   (KH_OFF + 2 * K_BUFB)      // 10752
#define V_OFF    (KL_OFF + 2 * K_BUFB)      // 15360
#define V_STRB   272                        // bytes per V row (128 bf16 + pad)
#define V_BUFB   (BN * V_STRB)              // 17408
#define SMEM_BYTES (V_OFF + 2 * V_BUFB)     // 50176  (x2 CTA = 100352)

__global__ void __launch_bounds__(128, 2)
flash_kernel(const float* __restrict__ xh,
             const float* __restrict__ gamma,
             float* __restrict__ out)
{
    extern __shared__ __align__(16) char smb[];
    u32 sb = (u32)__cvta_generic_to_shared(smb);

    int tid  = threadIdx.x;
    int warp = tid >> 5, lane = tid & 31;
    int b  = blockIdx.y;
    int i0 = blockIdx.x * BM;

    const float* qb = g_q + (size_t)b * NTOK * BD;
    const __nv_bfloat16* khb = g_khi + (size_t)b * BD * NTOK;
    const __nv_bfloat16* klb = g_klo + (size_t)b * BD * NTOK;
    const __nv_bfloat16* vb  = g_vb + (size_t)b * NTOK * CC;

    // ---- prologue: stage tile 0 K hi/lo ([d][key] rows) + V (token rows)
    {
        int d = tid >> 3, g16 = tid & 7;
        cp16s(sb + KH_OFF + (u32)(d * K_STRB + g16 * 16), khb + (size_t)d * NTOK + g16 * 8);
        cp16s(sb + KL_OFF + (u32)(d * K_STRB + g16 * 16), klb + (size_t)d * NTOK + g16 * 8);
    }
#pragma unroll
    for (int it = 0; it < 8; ++it) {
        int e = tid + it * 128;
        int k = e >> 4, c16 = e & 15;
        cp16s(sb + V_OFF + (u32)(k * V_STRB + c16 * 16), vb + (size_t)k * CC + c16 * 8);
    }
    CP_COMMIT();

    // ---- Q: fp32 -> bf16 hi/lo rows in smem
#pragma unroll
    for (int it = 0; it < 8; ++it) {
        int e = tid + it * 128;
        int tok = e >> 4, d = e & 15;
        float q = qb[(size_t)(i0 + tok) * BD + d];
        __nv_bfloat16 qh = __float2bfloat16(q);
        float qrem = q - __bfloat162float(qh);
        *(__nv_bfloat16*)(smb + QH_OFF + tok * Q_STRB + d * 2) = qh;
        *(__nv_bfloat16*)(smb + QL_OFF + tok * Q_STRB + d * 2) = __float2bfloat16(qrem);
    }
    __syncthreads();

    // ldmatrix lane addressing (constant per thread)
    int a_row  = (lane & 7) + ((lane >> 3) & 1) * 8;
    int a_csel = ((lane >> 4) & 1) * 16;
    int b_krow = (lane & 7) + ((lane >> 3) & 1) * 8;
    int b_csel = ((lane >> 4) & 1) * 16;

    // ---- Q A-fragments (loop-invariant)
    u32 Ah0, Ah1, Ah2, Ah3, Al0, Al1, Al2, Al3;
    LDSM_X4(Ah0, Ah1, Ah2, Ah3, sb + QH_OFF + (u32)((warp * 16 + a_row) * Q_STRB + a_csel));
    LDSM_X4(Al0, Al1, Al2, Al3, sb + QL_OFF + (u32)((warp * 16 + a_row) * Q_STRB + a_csel));

    float acc[16][4];                        // 16 n-blocks x m16n8 fragment
#pragma unroll
    for (int nb = 0; nb < 16; ++nb)
#pragma unroll
        for (int r = 0; r < 4; ++r) acc[nb][r] = 0.f;
    float lp0 = 0.f, lp1 = 0.f;              // per-thread partial row sums

    for (int t = 0; t < NT; ++t) {
        __syncthreads();   // prior tile's K/V reads done before overwrite

        if (t + 1 < NT) {
            int j1 = (t + 1) * BN;
            u32 buf = (u32)((t + 1) & 1);
            {
                int d = tid >> 3, g16 = tid & 7;
                cp16s(sb + KH_OFF + buf * K_BUFB + (u32)(d * K_STRB + g16 * 16),
                      khb + (size_t)d * NTOK + j1 + g16 * 8);
                cp16s(sb + KL_OFF + buf * K_BUFB + (u32)(d * K_STRB + g16 * 16),
                      klb + (size_t)d * NTOK + j1 + g16 * 8);
            }
#pragma unroll
            for (int it = 0; it < 8; ++it) {
                int e = tid + it * 128;
                int k = e >> 4, c16 = e & 15;
                cp16s(sb + V_OFF + buf * V_BUFB + (u32)(k * V_STRB + c16 * 16),
                      vb + (size_t)(j1 + k) * CC + c16 * 8);
            }
        }
        CP_COMMIT();
        CP_WAIT1();        // tile t resident
        __syncthreads();

        // ---- QK on tensor cores: s = Qh*Kh + Ql*Kh + Qh*Kl (bf16x3)
        u32 khbase = sb + KH_OFF + (u32)((t & 1) * K_BUFB) + (u32)(b_krow * K_STRB + b_csel);
        u32 klbase = sb + KL_OFF + (u32)((t & 1) * K_BUFB) + (u32)(b_krow * K_STRB + b_csel);
        float c[8][4];
#pragma unroll
        for (int nb = 0; nb < 8; ++nb)
#pragma unroll
            for (int r = 0; r < 4; ++r) c[nb][r] = 0.f;
#pragma unroll
        for (int g = 0; g < 4; ++g) {
            u32 h0, h1, h2, h3, l0, l1, l2, l3;
            LDSM_X4T(h0, h1, h2, h3, khbase + g * 32);
            LDSM_X4T(l0, l1, l2, l3, klbase + g * 32);
            MMA_BF16(c[2*g][0], c[2*g][1], c[2*g][2], c[2*g][3], Ah0, Ah1, Ah2, Ah3, h0, h1);
            MMA_BF16(c[2*g][0], c[2*g][1], c[2*g][2], c[2*g][3], Al0, Al1, Al2, Al3, h0, h1);
            MMA_BF16(c[2*g][0], c[2*g][1], c[2*g][2], c[2*g][3], Ah0, Ah1, Ah2, Ah3, l0, l1);
            MMA_BF16(c[2*g+1][0], c[2*g+1][1], c[2*g+1][2], c[2*g+1][3], Ah0, Ah1, Ah2, Ah3, h2, h3);
            MMA_BF16(c[2*g+1][0], c[2*g+1][1], c[2*g+1][2], c[2*g+1][3], Al0, Al1, Al2, Al3, h2, h3);
            MMA_BF16(c[2*g+1][0], c[2*g+1][1], c[2*g+1][2], c[2*g+1][3], Ah0, Ah1, Ah2, Ah3, l2, l3);
        }

        // ---- exp + pack P directly into A-fragments (no smem round-trip)
        u32 aP[4][4];
#pragma unroll
        for (int nb = 0; nb < 8; ++nb) {
            float p0 = __expf(c[nb][0]);
            float p1 = __expf(c[nb][1]);
            float p2 = __expf(c[nb][2]);
            float p3 = __expf(c[nb][3]);
            lp0 += p0 + p1;
            lp1 += p2 + p3;
            int ks = nb >> 1;
            if ((nb & 1) == 0) {
                aP[ks][0] = cvt2bf(p0, p1);
                aP[ks][1] = cvt2bf(p2, p3);
            } else {
                aP[ks][2] = cvt2bf(p0, p1);
                aP[ks][3] = cvt2bf(p2, p3);
            }
        }

        // ---- PV: 8 channel groups x 4 ksteps
        u32 vbase = sb + V_OFF + (u32)((t & 1) * V_BUFB);
#pragma unroll
        for (int nbp = 0; nbp < 8; ++nbp) {
#pragma unroll
            for (int ks = 0; ks < 4; ++ks) {
                u32 b0, b1, b2, b3;
                u32 baddr = vbase + (u32)((ks * 16 + b_krow) * V_STRB + nbp * 32 + b_csel);
                LDSM_X4T(b0, b1, b2, b3, baddr);
                MMA_BF16(acc[nbp * 2][0], acc[nbp * 2][1], acc[nbp * 2][2], acc[nbp * 2][3],
                         aP[ks][0], aP[ks][1], aP[ks][2], aP[ks][3], b0, b1);
                MMA_BF16(acc[nbp * 2 + 1][0], acc[nbp * 2 + 1][1],
                         acc[nbp * 2 + 1][2], acc[nbp * 2 + 1][3],
                         aP[ks][0], aP[ks][1], aP[ks][2], aP[ks][3], b2, b3);
            }
        }
    }

    // ---- l: quad reduce (rows r0/r0+8 shared by lanes 4k..4k+3)
    lp0 += __shfl_xor_sync(0xffffffffu, lp0, 1, 4);
    lp0 += __shfl_xor_sync(0xffffffffu, lp0, 2, 4);
    lp1 += __shfl_xor_sync(0xffffffffu, lp1, 1, 4);
    lp1 += __shfl_xor_sync(0xffffffffu, lp1, 2, 4);

    // ---- epilogue: out = gamma * acc / l + xh
    {
        float g = gamma[0];
        float inv0 = g / lp0;
        float inv1 = g / lp1;
        int r0 = warp * 16 + (lane >> 2);
#pragma unroll
        for (int nb = 0; nb < 16; ++nb) {
            int ch = nb * 8 + (lane & 3) * 2;
            size_t g00 = ((size_t)(b * CC + ch)) * NTOK + i0 + r0;
            size_t g01 = g00 + NTOK;
            out[g00]     = acc[nb][0] * inv0 + xh[g00];
            out[g01]     = acc[nb][1] * inv0 + xh[g01];
            out[g00 + 8] = acc[nb][2] * inv1 + xh[g00 + 8];
            out[g01 + 8] = acc[nb][3] * inv1 + xh[g01 + 8];
        }
    }
}

// ---------------------------------------------------------------------------
extern "C" void kernel_launch(void* const* d_in, const int* in_sizes, int n_in,
                              void* d_out, int out_size)
{
    const float* x     = (const float*)d_in[0];
    const float* xh    = (const float*)d_in[1];
    const float* Wq    = (const float*)d_in[2];
    const float* bq    = (const float*)d_in[3];
    const float* Wk    = (const float*)d_in[4];
    const float* bk    = (const float*)d_in[5];
    const float* Wv    = (const float*)d_in[6];
    const float* bv    = (const float*)d_in[7];
    const float* gamma = (const float*)d_in[8];
    float* out = (float*)d_out;

    (void)in_sizes; (void)n_in; (void)out_size;

    cudaFuncSetAttribute(flash_kernel, cudaFuncAttributeMaxDynamicSharedMemorySize, SMEM_BYTES);

    proj_kernel<<<dim3(16 + NTOK / 64, NB), 256>>>(x, Wq, bq, Wk, bk, xh, Wv, bv);
    flash_kernel<<<dim3(NTOK / BM, NB), 128, SMEM_BYTES>>>(xh, gamma, out);
}